// round 13
// baseline (speedup 1.0000x reference)
#include <cuda_runtime.h>
#include <cuda_fp16.h>
#include <cstdint>

#define NN 8192
#define KSPLIT 4
#define KCH (NN / KSPLIT)          // 2048
#define BK 64
#define NTILES (KCH / BK)          // 32
#define KSPLIT1 2                  // layer-1 fused kernel (1 CTA/SM)
#define KCH1 (NN / KSPLIT1)        // 4096
#define NTILES1 (KCH1 / BK)        // 64

// ---------------------------------------------------------------------------
// Scratch (no cudaMalloc allowed)
// ---------------------------------------------------------------------------
__device__ __half a16_dev[(size_t)NN * NN];           // A in fp16 (128 MB)
__device__ __half gt_h_dev[64 * NN];                  // G^T hi [D][NN], scaled
__device__ float  gt32_dev[64 * NN];                  // G^T fp32 (true scale)
__device__ float  part_buf_dev[(size_t)KSPLIT * NN * 64];  // split-K partials
__device__ unsigned g_max_dev[4];                     // monotone across replays

// ---------------------------------------------------------------------------
// PTX helpers (plain sm_103-legal)
// ---------------------------------------------------------------------------
__device__ __forceinline__ uint32_t smem_u32(const void* p) {
    uint32_t a;
    asm("{ .reg .u64 t; cvta.to.shared.u64 t, %1; cvt.u32.u64 %0, t; }"
        : "=r"(a) : "l"(p));
    return a;
}
__device__ __forceinline__ void cp16(uint32_t dst, const void* src) {
    asm volatile("cp.async.cg.shared.global [%0], [%1], 16;\n"
                 :: "r"(dst), "l"(src));
}
#define CP_COMMIT() asm volatile("cp.async.commit_group;" ::: "memory")
#define CP_WAIT0()  asm volatile("cp.async.wait_group 0;" ::: "memory")
#define CP_WAIT1()  asm volatile("cp.async.wait_group 1;" ::: "memory")
#define CP_WAIT2()  asm volatile("cp.async.wait_group 2;" ::: "memory")
#define SWZ128(x) ((x) ^ (((x) >> 3) & 0x70))

__device__ __forceinline__ void ldm4(uint32_t* a, uint32_t addr) {
    asm volatile("ldmatrix.sync.aligned.m8n8.x4.shared.b16 {%0,%1,%2,%3}, [%4];"
                 : "=r"(a[0]), "=r"(a[1]), "=r"(a[2]), "=r"(a[3]) : "r"(addr));
}
__device__ __forceinline__ void mma_f16(float* c, const uint32_t* a,
                                        uint32_t b0, uint32_t b1) {
    asm volatile(
        "mma.sync.aligned.m16n8k16.row.col.f32.f16.f16.f32 "
        "{%0,%1,%2,%3},{%4,%5,%6,%7},{%8,%9},{%0,%1,%2,%3};"
        : "+f"(c[0]), "+f"(c[1]), "+f"(c[2]), "+f"(c[3])
        : "r"(a[0]), "r"(a[1]), "r"(a[2]), "r"(a[3]), "r"(b0), "r"(b1));
}

// power-of-2 scale so max|g|*s <= 30000; identical math in every consumer
__device__ __forceinline__ float scale_of(int L) {
    float m = __uint_as_float(g_max_dev[L]);
    float s = 1.0f;
    if (m > 0.0f) s = exp2f(-ceilf(log2f(m / 30000.0f)));
    if (!(s > 0.0f) || isinf(s)) s = 1.0f;
    return s;
}

// ---------------------------------------------------------------------------
// Layer-1 fused kernel: converts A fp32 -> fp16 (writes a16_dev) AND computes
//   part[ks] = A @ G1.  BM=128, BK=64, 1 CTA/SM, 4 stages, distance 3.
// ---------------------------------------------------------------------------
__global__ void __launch_bounds__(256, 1)
conv_mma(const float* __restrict__ A) {
    constexpr int D    = 32;
    constexpr int NJ   = D / 16;           // 2
    constexpr int GPL  = D * 128;          // 4096
    constexpr int A32B = 128 * 256;        // 32768 (fp32 plane)
    constexpr int A16B = 128 * 128;        // 16384 (fp16 plane)
    constexpr int STAGE = A32B + A16B + GPL;  // 53248

    extern __shared__ __align__(1024) char smem[];
    const uint32_t sb = smem_u32(smem);
    const int tid  = threadIdx.x;
    const int wid  = tid >> 5;
    const int lane = tid & 31;
    const int rw   = wid >> 1;
    const int cw   = wid & 1;
    const size_t row0 = (size_t)blockIdx.x * 128;
    const size_t k0   = (size_t)blockIdx.y * KCH1;

    auto load_tile = [&](int st, int kt) {
        const uint32_t base = sb + st * STAGE;
        const size_t   ke   = k0 + (size_t)kt * BK;
        #pragma unroll
        for (int p = 0; p < 8; ++p) {
            const int c = p * 256 + tid;
            const int r = c >> 4, ch = c & 15;
            cp16(base + (uint32_t)(r * 256 + ch * 16),
                 A + (row0 + r) * NN + ke + ch * 4);
        }
        {
            const int r = tid >> 3, ch = tid & 7;
            cp16(base + A32B + A16B + SWZ128((uint32_t)(r * 128 + ch * 16)),
                 gt_h_dev + (size_t)r * NN + ke + ch * 8);
        }
    };

    float acc[2][NJ][4];
    #pragma unroll
    for (int mb = 0; mb < 2; ++mb)
        #pragma unroll
        for (int j = 0; j < NJ; ++j)
            #pragma unroll
            for (int q = 0; q < 4; ++q) acc[mb][j][q] = 0.0f;

    load_tile(0, 0); CP_COMMIT();
    load_tile(1, 1); CP_COMMIT();
    load_tile(2, 2); CP_COMMIT();

    for (int kt = 0; kt < NTILES1; ++kt) {
        if (kt < NTILES1 - 2)       CP_WAIT2();
        else if (kt == NTILES1 - 2) CP_WAIT1();
        else                        CP_WAIT0();
        __syncthreads();

        if (kt + 3 < NTILES1) { load_tile((kt + 3) & 3, kt + 3); CP_COMMIT(); }

        const int st = kt & 3;
        const uint32_t base = sb + st * STAGE;
        const size_t   ke   = k0 + (size_t)kt * BK;

        #pragma unroll
        for (int p = 0; p < 8; ++p) {
            const int c = p * 256 + tid;
            const int r = c >> 4, ch = c & 15;
            const float4 v = *(const float4*)(smem + st * STAGE + r * 256 + ch * 16);
            __half2 h01 = __floats2half2_rn(v.x, v.y);
            __half2 h23 = __floats2half2_rn(v.z, v.w);
            uint2 pk;
            pk.x = *reinterpret_cast<uint32_t*>(&h01);
            pk.y = *reinterpret_cast<uint32_t*>(&h23);
            *(uint2*)(a16_dev + (row0 + r) * NN + ke + ch * 4) = pk;
            *(uint2*)(smem + st * STAGE + A32B
                      + SWZ128((uint32_t)(r * 128 + ch * 8))) = pk;
        }
        __syncthreads();

        const uint32_t ab16 = base + A32B;
        uint32_t Ar[2][4][4];
        #pragma unroll
        for (int mb = 0; mb < 2; ++mb)
            #pragma unroll
            for (int kk = 0; kk < 4; ++kk)
                ldm4(Ar[mb][kk], ab16 + SWZ128((uint32_t)(
                    (rw * 32 + mb * 16 + (lane & 15)) * 128
                    + kk * 32 + (lane >> 4) * 16)));

        const uint32_t gb = base + A32B + A16B;
        #pragma unroll
        for (int j = 0; j < NJ; ++j) {
            const uint32_t nrow = (uint32_t)((cw * (D / 2) + j * 8 + (lane & 7)) * 128
                                             + (lane >> 3) * 16);
            uint32_t bh[8];
            ldm4(bh,     gb + SWZ128(nrow));
            ldm4(bh + 4, gb + SWZ128(nrow + 64));
            #pragma unroll
            for (int mb = 0; mb < 2; ++mb) {
                float* c = acc[mb][j];
                #pragma unroll
                for (int kk = 0; kk < 4; ++kk)
                    mma_f16(c, Ar[mb][kk], bh[2 * kk], bh[2 * kk + 1]);
            }
        }
    }

    float* P = part_buf_dev
             + ((size_t)blockIdx.y * NN + row0 + rw * 32) * D + cw * (D / 2);
    const int r0 = lane >> 2;
    const int c0 = (lane & 3) * 2;
    #pragma unroll
    for (int mb = 0; mb < 2; ++mb)
        #pragma unroll
        for (int j = 0; j < NJ; ++j) {
            float* c = acc[mb][j];
            *(float2*)&P[(size_t)(mb * 16 + r0) * D + j * 8 + c0]     = make_float2(c[0], c[1]);
            *(float2*)&P[(size_t)(mb * 16 + r0 + 8) * D + j * 8 + c0] = make_float2(c[2], c[3]);
        }
}

// ---------------------------------------------------------------------------
// Big GEMM (layers 2-4): part[ks] = A16 @ Gscaled_hi, 4 stages, distance 3.
// ---------------------------------------------------------------------------
template<int D>
__global__ void __launch_bounds__(256, 2)
big_mma() {
    constexpr int NJ    = D / 16;
    constexpr int GPL   = D * 128;
    constexpr int ATB   = 128 * 128;
    constexpr int STAGE = ATB + GPL;
    constexpr int GCHK  = D * 8;

    extern __shared__ __align__(1024) char smem[];
    const uint32_t sb = smem_u32(smem);
    const int tid  = threadIdx.x;
    const int wid  = tid >> 5;
    const int lane = tid & 31;
    const int rw   = wid >> 1;
    const int cw   = wid & 1;
    const size_t row0 = (size_t)blockIdx.x * 128;
    const size_t k0   = (size_t)blockIdx.y * KCH;

    auto load_tile = [&](int st, int kt) {
        const uint32_t base = sb + st * STAGE;
        const size_t   ke   = k0 + (size_t)kt * BK;
        #pragma unroll
        for (int p = 0; p < 4; ++p) {
            const int c = p * 256 + tid;
            const int r = c >> 3, ch = c & 7;
            cp16(base + SWZ128((uint32_t)(r * 128 + ch * 16)),
                 a16_dev + (row0 + r) * NN + ke + ch * 8);
        }
        #pragma unroll
        for (int p = 0; p < GCHK / 256; ++p) {
            const int c = p * 256 + tid;
            const int r = c >> 3, ch = c & 7;
            cp16(base + ATB + SWZ128((uint32_t)(r * 128 + ch * 16)),
                 gt_h_dev + (size_t)r * NN + ke + ch * 8);
        }
    };

    float acc[2][NJ][4];
    #pragma unroll
    for (int mb = 0; mb < 2; ++mb)
        #pragma unroll
        for (int j = 0; j < NJ; ++j)
            #pragma unroll
            for (int q = 0; q < 4; ++q) acc[mb][j][q] = 0.0f;

    load_tile(0, 0); CP_COMMIT();
    load_tile(1, 1); CP_COMMIT();
    load_tile(2, 2); CP_COMMIT();

    for (int kt = 0; kt < NTILES; ++kt) {
        if (kt < NTILES - 2)       CP_WAIT2();
        else if (kt == NTILES - 2) CP_WAIT1();
        else                       CP_WAIT0();
        __syncthreads();

        if (kt + 3 < NTILES) { load_tile((kt + 3) & 3, kt + 3); CP_COMMIT(); }

        const uint32_t base = sb + (kt & 3) * STAGE;

        uint32_t Ar[2][4][4];
        #pragma unroll
        for (int mb = 0; mb < 2; ++mb)
            #pragma unroll
            for (int kk = 0; kk < 4; ++kk)
                ldm4(Ar[mb][kk], base + SWZ128((uint32_t)(
                    (rw * 32 + mb * 16 + (lane & 15)) * 128
                    + kk * 32 + (lane >> 4) * 16)));

        const uint32_t gb = base + ATB;
        #pragma unroll
        for (int j = 0; j < NJ; ++j) {
            const uint32_t nrow = (uint32_t)((cw * (D / 2) + j * 8 + (lane & 7)) * 128
                                             + (lane >> 3) * 16);
            uint32_t bh[8];
            ldm4(bh,     gb + SWZ128(nrow));
            ldm4(bh + 4, gb + SWZ128(nrow + 64));
            #pragma unroll
            for (int mb = 0; mb < 2; ++mb) {
                float* c = acc[mb][j];
                #pragma unroll
                for (int kk = 0; kk < 4; ++kk)
                    mma_f16(c, Ar[mb][kk], bh[2 * kk], bh[2 * kk + 1]);
            }
        }
    }

    float* P = part_buf_dev
             + ((size_t)blockIdx.y * NN + row0 + rw * 32) * D + cw * (D / 2);
    const int r0 = lane >> 2;
    const int c0 = (lane & 3) * 2;
    #pragma unroll
    for (int mb = 0; mb < 2; ++mb)
        #pragma unroll
        for (int j = 0; j < NJ; ++j) {
            float* c = acc[mb][j];
            *(float2*)&P[(size_t)(mb * 16 + r0) * D + j * 8 + c0]     = make_float2(c[0], c[1]);
            *(float2*)&P[(size_t)(mb * 16 + r0 + 8) * D + j * 8 + c0] = make_float2(c[2], c[3]);
        }
}

// ---------------------------------------------------------------------------
// Row-wise: 8 threads per row (q = tid&7 computes DOUT/8 outputs).
//   32 rows per 256-thread block -> grid 256 (~2 blocks/SM, 16 warps/SM).
//   W read via float4 LDS (4x fewer shared-load instructions).
// ---------------------------------------------------------------------------
template<int DIN, int DOUT, int KS, bool RELU, int LAYER, int PREV>
__global__ void __launch_bounds__(256)
row_gemm(const float* __restrict__ xsrc, const float* __restrict__ W) {
    constexpr int JQ = DOUT / 8;           // outputs per thread
    __shared__ float Ws[DOUT * DIN];
    for (int i = threadIdx.x; i < DOUT * DIN; i += 256) Ws[i] = W[i];
    __syncthreads();

    const float inv = (PREV >= 0) ? (1.0f / scale_of(PREV)) : 1.0f;
    const float* __restrict__ src = (PREV >= 0) ? part_buf_dev : xsrc;
    const int q = threadIdx.x & 7;         // output octant
    const int r = blockIdx.x * 32 + (threadIdx.x >> 3);

    float h[DIN];
    #pragma unroll
    for (int i4 = 0; i4 < DIN / 4; ++i4) {
        float4 v = *(const float4*)(src + (size_t)r * DIN + i4 * 4);
        h[4 * i4 + 0] = v.x; h[4 * i4 + 1] = v.y;
        h[4 * i4 + 2] = v.z; h[4 * i4 + 3] = v.w;
    }
    #pragma unroll
    for (int s = 1; s < KS; ++s)
        #pragma unroll
        for (int i4 = 0; i4 < DIN / 4; ++i4) {
            float4 v = *(const float4*)(src + ((size_t)s * NN + r) * DIN + i4 * 4);
            h[4 * i4 + 0] += v.x; h[4 * i4 + 1] += v.y;
            h[4 * i4 + 2] += v.z; h[4 * i4 + 3] += v.w;
        }
    #pragma unroll
    for (int i = 0; i < DIN; ++i) {
        h[i] *= inv;
        if (RELU) h[i] = fmaxf(h[i], 0.0f);
    }

    float m = 0.0f;
    #pragma unroll
    for (int jj = 0; jj < JQ; ++jj) {
        const int j = q * JQ + jj;
        float a = 0.0f;
        const float4* w4 = (const float4*)&Ws[j * DIN];
        #pragma unroll
        for (int i4 = 0; i4 < DIN / 4; ++i4) {
            const float4 wv = w4[i4];
            a = fmaf(h[4 * i4 + 0], wv.x, a);
            a = fmaf(h[4 * i4 + 1], wv.y, a);
            a = fmaf(h[4 * i4 + 2], wv.z, a);
            a = fmaf(h[4 * i4 + 3], wv.w, a);
        }
        gt32_dev[(size_t)j * NN + r] = a;
        m = fmaxf(m, fabsf(a));
    }
    #pragma unroll
    for (int o = 16; o; o >>= 1)
        m = fmaxf(m, __shfl_xor_sync(0xFFFFFFFFu, m, o));
    if ((threadIdx.x & 31) == 0)
        atomicMax(&g_max_dev[LAYER], __float_as_uint(m));
}

// ---------------------------------------------------------------------------
// Convert: G^T fp32 -> scaled fp16; fully coalesced
// ---------------------------------------------------------------------------
__global__ void __launch_bounds__(256)
convert_g(int L) {
    const size_t i = (size_t)blockIdx.x * 256 + threadIdx.x;
    const float s = scale_of(L);
    gt_h_dev[i] = __float2half_rn(gt32_dev[i] * s);
}

// ---------------------------------------------------------------------------
// Final reduce: out = inv_s4 * sum of KSPLIT partials
// ---------------------------------------------------------------------------
__global__ void __launch_bounds__(256)
reduce_out(float* __restrict__ out) {
    const int idx = blockIdx.x * 256 + threadIdx.x;
    const float4* p4 = (const float4*)part_buf_dev;
    float4 a = p4[idx];
    #pragma unroll
    for (int s = 1; s < KSPLIT; ++s) {
        float4 b = p4[(size_t)s * (NN * 32 / 4) + idx];
        a.x += b.x; a.y += b.y; a.z += b.z; a.w += b.w;
    }
    const float inv = 1.0f / scale_of(3);
    a.x *= inv; a.y *= inv; a.z *= inv; a.w *= inv;
    ((float4*)out)[idx] = a;
}

// ---------------------------------------------------------------------------
// Launch
// ---------------------------------------------------------------------------
extern "C" void kernel_launch(void* const* d_in, const int* in_sizes, int n_in,
                              void* d_out, int out_size) {
    (void)in_sizes; (void)n_in; (void)out_size;
    const float* A  = (const float*)d_in[0];
    const float* X  = (const float*)d_in[1];
    const float* W1 = (const float*)d_in[2];
    const float* W2 = (const float*)d_in[3];
    const float* W3 = (const float*)d_in[4];
    const float* W4 = (const float*)d_in[5];
    float* out = (float*)d_out;

    constexpr int SMC  = 4 * (32768 + 16384 + 32 * 128);   // 212992
    constexpr int SM32 = 4 * (16384 + 32 * 128);           // 81920
    constexpr int SM64 = 4 * (16384 + 64 * 128);           // 98304
    cudaFuncSetAttribute(conv_mma,    cudaFuncAttributeMaxDynamicSharedMemorySize, SMC);
    cudaFuncSetAttribute(big_mma<32>, cudaFuncAttributeMaxDynamicSharedMemorySize, SM32);
    cudaFuncSetAttribute(big_mma<64>, cudaFuncAttributeMaxDynamicSharedMemorySize, SM64);

    const dim3 big_grid(NN / 128, KSPLIT);     // 256 CTAs (single wave @2/SM)
    const dim3 conv_grid(NN / 128, KSPLIT1);   // 128 CTAs (single wave @1/SM)

    // Layer 1: G1 = X @ W1^T ; fused A-convert + P = A @ G1
    row_gemm<32, 32, 1, false, 0, -1><<<NN / 32, 256>>>(X, W1);
    convert_g<<<NN * 32 / 256, 256>>>(0);
    conv_mma<<<conv_grid, 256, SMC>>>(A);
    // Layer 2 (partials from layer 1 have KSPLIT1 splits)
    row_gemm<32, 64, KSPLIT1, true, 1, 0><<<NN / 32, 256>>>(nullptr, W2);
    convert_g<<<NN * 64 / 256, 256>>>(1);
    big_mma<64><<<big_grid, 256, SM64>>>();
    // Layer 3
    row_gemm<64, 64, KSPLIT, true, 2, 1><<<NN / 32, 256>>>(nullptr, W3);
    convert_g<<<NN * 64 / 256, 256>>>(2);
    big_mma<64><<<big_grid, 256, SM64>>>();
    // Layer 4
    row_gemm<64, 32, KSPLIT, true, 3, 2><<<NN / 32, 256>>>(nullptr, W4);
    convert_g<<<NN * 32 / 256, 256>>>(3);
    big_mma<32><<<big_grid, 256, SM32>>>();

    reduce_out<<<NN * 32 / 4 / 256, 256>>>(out);
}

// round 14
// speedup vs baseline: 1.2013x; 1.2013x over previous
#include <cuda_runtime.h>
#include <cuda_fp16.h>
#include <cstdint>

#define NN 8192
#define KSPLIT 4
#define KCH (NN / KSPLIT)          // 2048
#define BK 64
#define NTILES (KCH / BK)          // 32
#define KSPLIT1 2                  // layer-1 fused kernel (1 CTA/SM)
#define KCH1 (NN / KSPLIT1)        // 4096
#define NTILES1 (KCH1 / BK)        // 64

// ---------------------------------------------------------------------------
// Scratch (no cudaMalloc allowed)
// ---------------------------------------------------------------------------
__device__ __half a16_dev[(size_t)NN * NN];           // A in fp16 (128 MB)
__device__ __half gt_h_dev[64 * NN];                  // G^T hi [D][NN], scaled
__device__ float  gt32_dev[64 * NN];                  // G^T fp32 (true scale)
__device__ float  part_buf_dev[(size_t)KSPLIT * NN * 64];  // split-K partials
__device__ unsigned g_max_dev[4];                     // monotone across replays

// ---------------------------------------------------------------------------
// PTX helpers (plain sm_103-legal)
// ---------------------------------------------------------------------------
__device__ __forceinline__ uint32_t smem_u32(const void* p) {
    uint32_t a;
    asm("{ .reg .u64 t; cvta.to.shared.u64 t, %1; cvt.u32.u64 %0, t; }"
        : "=r"(a) : "l"(p));
    return a;
}
__device__ __forceinline__ void cp16(uint32_t dst, const void* src) {
    asm volatile("cp.async.cg.shared.global [%0], [%1], 16;\n"
                 :: "r"(dst), "l"(src));
}
#define CP_COMMIT() asm volatile("cp.async.commit_group;" ::: "memory")
#define CP_WAIT0()  asm volatile("cp.async.wait_group 0;" ::: "memory")
#define CP_WAIT1()  asm volatile("cp.async.wait_group 1;" ::: "memory")
#define CP_WAIT2()  asm volatile("cp.async.wait_group 2;" ::: "memory")
#define SWZ128(x) ((x) ^ (((x) >> 3) & 0x70))

__device__ __forceinline__ void ldm4(uint32_t* a, uint32_t addr) {
    asm volatile("ldmatrix.sync.aligned.m8n8.x4.shared.b16 {%0,%1,%2,%3}, [%4];"
                 : "=r"(a[0]), "=r"(a[1]), "=r"(a[2]), "=r"(a[3]) : "r"(addr));
}
__device__ __forceinline__ void mma_f16(float* c, const uint32_t* a,
                                        uint32_t b0, uint32_t b1) {
    asm volatile(
        "mma.sync.aligned.m16n8k16.row.col.f32.f16.f16.f32 "
        "{%0,%1,%2,%3},{%4,%5,%6,%7},{%8,%9},{%0,%1,%2,%3};"
        : "+f"(c[0]), "+f"(c[1]), "+f"(c[2]), "+f"(c[3])
        : "r"(a[0]), "r"(a[1]), "r"(a[2]), "r"(a[3]), "r"(b0), "r"(b1));
}

// power-of-2 scale so max|g|*s <= 30000; identical math in every consumer
__device__ __forceinline__ float scale_of(int L) {
    float m = __uint_as_float(g_max_dev[L]);
    float s = 1.0f;
    if (m > 0.0f) s = exp2f(-ceilf(log2f(m / 30000.0f)));
    if (!(s > 0.0f) || isinf(s)) s = 1.0f;
    return s;
}

// ---------------------------------------------------------------------------
// Layer-1 fused kernel: converts A fp32 -> fp16 (writes a16_dev) AND computes
//   part[ks] = A @ G1.  BM=128, BK=64, 1 CTA/SM, 4 stages, distance 3.
// ---------------------------------------------------------------------------
__global__ void __launch_bounds__(256, 1)
conv_mma(const float* __restrict__ A) {
    constexpr int D    = 32;
    constexpr int NJ   = D / 16;           // 2
    constexpr int GPL  = D * 128;          // 4096
    constexpr int A32B = 128 * 256;        // 32768 (fp32 plane)
    constexpr int A16B = 128 * 128;        // 16384 (fp16 plane)
    constexpr int STAGE = A32B + A16B + GPL;  // 53248

    extern __shared__ __align__(1024) char smem[];
    const uint32_t sb = smem_u32(smem);
    const int tid  = threadIdx.x;
    const int wid  = tid >> 5;
    const int lane = tid & 31;
    const int rw   = wid >> 1;
    const int cw   = wid & 1;
    const size_t row0 = (size_t)blockIdx.x * 128;
    const size_t k0   = (size_t)blockIdx.y * KCH1;

    auto load_tile = [&](int st, int kt) {
        const uint32_t base = sb + st * STAGE;
        const size_t   ke   = k0 + (size_t)kt * BK;
        #pragma unroll
        for (int p = 0; p < 8; ++p) {
            const int c = p * 256 + tid;
            const int r = c >> 4, ch = c & 15;
            cp16(base + (uint32_t)(r * 256 + ch * 16),
                 A + (row0 + r) * NN + ke + ch * 4);
        }
        {
            const int r = tid >> 3, ch = tid & 7;
            cp16(base + A32B + A16B + SWZ128((uint32_t)(r * 128 + ch * 16)),
                 gt_h_dev + (size_t)r * NN + ke + ch * 8);
        }
    };

    float acc[2][NJ][4];
    #pragma unroll
    for (int mb = 0; mb < 2; ++mb)
        #pragma unroll
        for (int j = 0; j < NJ; ++j)
            #pragma unroll
            for (int q = 0; q < 4; ++q) acc[mb][j][q] = 0.0f;

    load_tile(0, 0); CP_COMMIT();
    load_tile(1, 1); CP_COMMIT();
    load_tile(2, 2); CP_COMMIT();

    for (int kt = 0; kt < NTILES1; ++kt) {
        if (kt < NTILES1 - 2)       CP_WAIT2();
        else if (kt == NTILES1 - 2) CP_WAIT1();
        else                        CP_WAIT0();
        __syncthreads();

        if (kt + 3 < NTILES1) { load_tile((kt + 3) & 3, kt + 3); CP_COMMIT(); }

        const int st = kt & 3;
        const uint32_t base = sb + st * STAGE;
        const size_t   ke   = k0 + (size_t)kt * BK;

        #pragma unroll
        for (int p = 0; p < 8; ++p) {
            const int c = p * 256 + tid;
            const int r = c >> 4, ch = c & 15;
            const float4 v = *(const float4*)(smem + st * STAGE + r * 256 + ch * 16);
            __half2 h01 = __floats2half2_rn(v.x, v.y);
            __half2 h23 = __floats2half2_rn(v.z, v.w);
            uint2 pk;
            pk.x = *reinterpret_cast<uint32_t*>(&h01);
            pk.y = *reinterpret_cast<uint32_t*>(&h23);
            *(uint2*)(a16_dev + (row0 + r) * NN + ke + ch * 4) = pk;
            *(uint2*)(smem + st * STAGE + A32B
                      + SWZ128((uint32_t)(r * 128 + ch * 8))) = pk;
        }
        __syncthreads();

        const uint32_t ab16 = base + A32B;
        uint32_t Ar[2][4][4];
        #pragma unroll
        for (int mb = 0; mb < 2; ++mb)
            #pragma unroll
            for (int kk = 0; kk < 4; ++kk)
                ldm4(Ar[mb][kk], ab16 + SWZ128((uint32_t)(
                    (rw * 32 + mb * 16 + (lane & 15)) * 128
                    + kk * 32 + (lane >> 4) * 16)));

        const uint32_t gb = base + A32B + A16B;
        #pragma unroll
        for (int j = 0; j < NJ; ++j) {
            const uint32_t nrow = (uint32_t)((cw * (D / 2) + j * 8 + (lane & 7)) * 128
                                             + (lane >> 3) * 16);
            uint32_t bh[8];
            ldm4(bh,     gb + SWZ128(nrow));
            ldm4(bh + 4, gb + SWZ128(nrow + 64));
            #pragma unroll
            for (int mb = 0; mb < 2; ++mb) {
                float* c = acc[mb][j];
                #pragma unroll
                for (int kk = 0; kk < 4; ++kk)
                    mma_f16(c, Ar[mb][kk], bh[2 * kk], bh[2 * kk + 1]);
            }
        }
    }

    float* P = part_buf_dev
             + ((size_t)blockIdx.y * NN + row0 + rw * 32) * D + cw * (D / 2);
    const int r0 = lane >> 2;
    const int c0 = (lane & 3) * 2;
    #pragma unroll
    for (int mb = 0; mb < 2; ++mb)
        #pragma unroll
        for (int j = 0; j < NJ; ++j) {
            float* c = acc[mb][j];
            *(float2*)&P[(size_t)(mb * 16 + r0) * D + j * 8 + c0]     = make_float2(c[0], c[1]);
            *(float2*)&P[(size_t)(mb * 16 + r0 + 8) * D + j * 8 + c0] = make_float2(c[2], c[3]);
        }
}

// ---------------------------------------------------------------------------
// Big GEMM (layers 2-4): part[ks] = A16 @ Gscaled_hi, 4 stages, distance 3.
// ---------------------------------------------------------------------------
template<int D>
__global__ void __launch_bounds__(256, 2)
big_mma() {
    constexpr int NJ    = D / 16;
    constexpr int GPL   = D * 128;
    constexpr int ATB   = 128 * 128;
    constexpr int STAGE = ATB + GPL;
    constexpr int GCHK  = D * 8;

    extern __shared__ __align__(1024) char smem[];
    const uint32_t sb = smem_u32(smem);
    const int tid  = threadIdx.x;
    const int wid  = tid >> 5;
    const int lane = tid & 31;
    const int rw   = wid >> 1;
    const int cw   = wid & 1;
    const size_t row0 = (size_t)blockIdx.x * 128;
    const size_t k0   = (size_t)blockIdx.y * KCH;

    auto load_tile = [&](int st, int kt) {
        const uint32_t base = sb + st * STAGE;
        const size_t   ke   = k0 + (size_t)kt * BK;
        #pragma unroll
        for (int p = 0; p < 4; ++p) {
            const int c = p * 256 + tid;
            const int r = c >> 3, ch = c & 7;
            cp16(base + SWZ128((uint32_t)(r * 128 + ch * 16)),
                 a16_dev + (row0 + r) * NN + ke + ch * 8);
        }
        #pragma unroll
        for (int p = 0; p < GCHK / 256; ++p) {
            const int c = p * 256 + tid;
            const int r = c >> 3, ch = c & 7;
            cp16(base + ATB + SWZ128((uint32_t)(r * 128 + ch * 16)),
                 gt_h_dev + (size_t)r * NN + ke + ch * 8);
        }
    };

    float acc[2][NJ][4];
    #pragma unroll
    for (int mb = 0; mb < 2; ++mb)
        #pragma unroll
        for (int j = 0; j < NJ; ++j)
            #pragma unroll
            for (int q = 0; q < 4; ++q) acc[mb][j][q] = 0.0f;

    load_tile(0, 0); CP_COMMIT();
    load_tile(1, 1); CP_COMMIT();
    load_tile(2, 2); CP_COMMIT();

    for (int kt = 0; kt < NTILES; ++kt) {
        if (kt < NTILES - 2)       CP_WAIT2();
        else if (kt == NTILES - 2) CP_WAIT1();
        else                       CP_WAIT0();
        __syncthreads();

        if (kt + 3 < NTILES) { load_tile((kt + 3) & 3, kt + 3); CP_COMMIT(); }

        const uint32_t base = sb + (kt & 3) * STAGE;

        uint32_t Ar[2][4][4];
        #pragma unroll
        for (int mb = 0; mb < 2; ++mb)
            #pragma unroll
            for (int kk = 0; kk < 4; ++kk)
                ldm4(Ar[mb][kk], base + SWZ128((uint32_t)(
                    (rw * 32 + mb * 16 + (lane & 15)) * 128
                    + kk * 32 + (lane >> 4) * 16)));

        const uint32_t gb = base + ATB;
        #pragma unroll
        for (int j = 0; j < NJ; ++j) {
            const uint32_t nrow = (uint32_t)((cw * (D / 2) + j * 8 + (lane & 7)) * 128
                                             + (lane >> 3) * 16);
            uint32_t bh[8];
            ldm4(bh,     gb + SWZ128(nrow));
            ldm4(bh + 4, gb + SWZ128(nrow + 64));
            #pragma unroll
            for (int mb = 0; mb < 2; ++mb) {
                float* c = acc[mb][j];
                #pragma unroll
                for (int kk = 0; kk < 4; ++kk)
                    mma_f16(c, Ar[mb][kk], bh[2 * kk], bh[2 * kk + 1]);
            }
        }
    }

    float* P = part_buf_dev
             + ((size_t)blockIdx.y * NN + row0 + rw * 32) * D + cw * (D / 2);
    const int r0 = lane >> 2;
    const int c0 = (lane & 3) * 2;
    #pragma unroll
    for (int mb = 0; mb < 2; ++mb)
        #pragma unroll
        for (int j = 0; j < NJ; ++j) {
            float* c = acc[mb][j];
            *(float2*)&P[(size_t)(mb * 16 + r0) * D + j * 8 + c0]     = make_float2(c[0], c[1]);
            *(float2*)&P[(size_t)(mb * 16 + r0 + 8) * D + j * 8 + c0] = make_float2(c[2], c[3]);
        }
}

// ---------------------------------------------------------------------------
// Row-wise: 4 threads per row (q = tid&3 computes DOUT/4 outputs).
//   64 rows per 256-thread block -> grid 128.
//   Max reduction: warp shfl -> smem -> ONE atomicMax per block (atomics to
//   the same L2 address serialize; per-warp atomics cost ~10us at grid 128).
// ---------------------------------------------------------------------------
template<int DIN, int DOUT, int KS, bool RELU, int LAYER, int PREV>
__global__ void __launch_bounds__(256)
row_gemm(const float* __restrict__ xsrc, const float* __restrict__ W) {
    constexpr int JQ = DOUT / 4;           // outputs per thread
    __shared__ float Ws[DOUT * DIN];
    __shared__ float wmax[8];
    for (int i = threadIdx.x; i < DOUT * DIN; i += 256) Ws[i] = W[i];
    __syncthreads();

    const float inv = (PREV >= 0) ? (1.0f / scale_of(PREV)) : 1.0f;
    const float* __restrict__ src = (PREV >= 0) ? part_buf_dev : xsrc;
    const int q = threadIdx.x & 3;         // output quarter
    const int r = blockIdx.x * 64 + (threadIdx.x >> 2);

    float h[DIN];
    #pragma unroll
    for (int i4 = 0; i4 < DIN / 4; ++i4) {
        float4 v = *(const float4*)(src + (size_t)r * DIN + i4 * 4);
        h[4 * i4 + 0] = v.x; h[4 * i4 + 1] = v.y;
        h[4 * i4 + 2] = v.z; h[4 * i4 + 3] = v.w;
    }
    #pragma unroll
    for (int s = 1; s < KS; ++s)
        #pragma unroll
        for (int i4 = 0; i4 < DIN / 4; ++i4) {
            float4 v = *(const float4*)(src + ((size_t)s * NN + r) * DIN + i4 * 4);
            h[4 * i4 + 0] += v.x; h[4 * i4 + 1] += v.y;
            h[4 * i4 + 2] += v.z; h[4 * i4 + 3] += v.w;
        }
    #pragma unroll
    for (int i = 0; i < DIN; ++i) {
        h[i] *= inv;
        if (RELU) h[i] = fmaxf(h[i], 0.0f);
    }

    float m = 0.0f;
    #pragma unroll
    for (int jj = 0; jj < JQ; ++jj) {
        const int j = q * JQ + jj;
        float a = 0.0f;
        const float* w = &Ws[j * DIN];
        #pragma unroll
        for (int i = 0; i < DIN; ++i) a = fmaf(h[i], w[i], a);
        gt32_dev[(size_t)j * NN + r] = a;
        m = fmaxf(m, fabsf(a));
    }
    #pragma unroll
    for (int o = 16; o; o >>= 1)
        m = fmaxf(m, __shfl_xor_sync(0xFFFFFFFFu, m, o));
    if ((threadIdx.x & 31) == 0) wmax[threadIdx.x >> 5] = m;
    __syncthreads();
    if (threadIdx.x == 0) {
        float mm = wmax[0];
        #pragma unroll
        for (int w = 1; w < 8; ++w) mm = fmaxf(mm, wmax[w]);
        atomicMax(&g_max_dev[LAYER], __float_as_uint(mm));
    }
}

// ---------------------------------------------------------------------------
// Convert: G^T fp32 -> scaled fp16; fully coalesced
// ---------------------------------------------------------------------------
__global__ void __launch_bounds__(256)
convert_g(int L) {
    const size_t i = (size_t)blockIdx.x * 256 + threadIdx.x;
    const float s = scale_of(L);
    gt_h_dev[i] = __float2half_rn(gt32_dev[i] * s);
}

// ---------------------------------------------------------------------------
// Final reduce: out = inv_s4 * sum of KSPLIT partials
// ---------------------------------------------------------------------------
__global__ void __launch_bounds__(256)
reduce_out(float* __restrict__ out) {
    const int idx = blockIdx.x * 256 + threadIdx.x;
    const float4* p4 = (const float4*)part_buf_dev;
    float4 a = p4[idx];
    #pragma unroll
    for (int s = 1; s < KSPLIT; ++s) {
        float4 b = p4[(size_t)s * (NN * 32 / 4) + idx];
        a.x += b.x; a.y += b.y; a.z += b.z; a.w += b.w;
    }
    const float inv = 1.0f / scale_of(3);
    a.x *= inv; a.y *= inv; a.z *= inv; a.w *= inv;
    ((float4*)out)[idx] = a;
}

// ---------------------------------------------------------------------------
// Launch
// ---------------------------------------------------------------------------
extern "C" void kernel_launch(void* const* d_in, const int* in_sizes, int n_in,
                              void* d_out, int out_size) {
    (void)in_sizes; (void)n_in; (void)out_size;
    const float* A  = (const float*)d_in[0];
    const float* X  = (const float*)d_in[1];
    const float* W1 = (const float*)d_in[2];
    const float* W2 = (const float*)d_in[3];
    const float* W3 = (const float*)d_in[4];
    const float* W4 = (const float*)d_in[5];
    float* out = (float*)d_out;

    constexpr int SMC  = 4 * (32768 + 16384 + 32 * 128);   // 212992
    constexpr int SM32 = 4 * (16384 + 32 * 128);           // 81920
    constexpr int SM64 = 4 * (16384 + 64 * 128);           // 98304
    cudaFuncSetAttribute(conv_mma,    cudaFuncAttributeMaxDynamicSharedMemorySize, SMC);
    cudaFuncSetAttribute(big_mma<32>, cudaFuncAttributeMaxDynamicSharedMemorySize, SM32);
    cudaFuncSetAttribute(big_mma<64>, cudaFuncAttributeMaxDynamicSharedMemorySize, SM64);

    const dim3 big_grid(NN / 128, KSPLIT);     // 256 CTAs (single wave @2/SM)
    const dim3 conv_grid(NN / 128, KSPLIT1);   // 128 CTAs (single wave @1/SM)

    // Layer 1: G1 = X @ W1^T ; fused A-convert + P = A @ G1
    row_gemm<32, 32, 1, false, 0, -1><<<NN / 64, 256>>>(X, W1);
    convert_g<<<NN * 32 / 256, 256>>>(0);
    conv_mma<<<conv_grid, 256, SMC>>>(A);
    // Layer 2 (partials from layer 1 have KSPLIT1 splits)
    row_gemm<32, 64, KSPLIT1, true, 1, 0><<<NN / 64, 256>>>(nullptr, W2);
    convert_g<<<NN * 64 / 256, 256>>>(1);
    big_mma<64><<<big_grid, 256, SM64>>>();
    // Layer 3
    row_gemm<64, 64, KSPLIT, true, 2, 1><<<NN / 64, 256>>>(nullptr, W3);
    convert_g<<<NN * 64 / 256, 256>>>(2);
    big_mma<64><<<big_grid, 256, SM64>>>();
    // Layer 4
    row_gemm<64, 32, KSPLIT, true, 3, 2><<<NN / 64, 256>>>(nullptr, W4);
    convert_g<<<NN * 32 / 256, 256>>>(3);
    big_mma<32><<<big_grid, 256, SM32>>>();

    reduce_out<<<NN * 32 / 4 / 256, 256>>>(out);
}

// round 15
// speedup vs baseline: 1.2550x; 1.0447x over previous
#include <cuda_runtime.h>
#include <cuda_fp16.h>
#include <cstdint>

#define NN 8192
#define KSPLIT 4
#define KCH (NN / KSPLIT)          // 2048
#define BK 64
#define NTILES (KCH / BK)          // 32
#define KSPLIT1 2                  // layer-1 fused kernel (1 CTA/SM)
#define KCH1 (NN / KSPLIT1)        // 4096
#define NTILES1 (KCH1 / BK)        // 64

// ---------------------------------------------------------------------------
// Scratch (no cudaMalloc allowed)
// ---------------------------------------------------------------------------
__device__ __half a16_dev[(size_t)NN * NN];           // A in fp16 (128 MB)
__device__ __half gt_h_dev[64 * NN];                  // G^T hi [D][NN], scaled
__device__ float  gt32_dev[64 * NN];                  // G^T fp32 (true scale)
__device__ float  part_buf_dev[(size_t)KSPLIT * NN * 64];  // split-K partials
__device__ unsigned g_max_dev[4];                     // monotone across replays

// ---------------------------------------------------------------------------
// PTX helpers (plain sm_103-legal)
// ---------------------------------------------------------------------------
__device__ __forceinline__ uint32_t smem_u32(const void* p) {
    uint32_t a;
    asm("{ .reg .u64 t; cvta.to.shared.u64 t, %1; cvt.u32.u64 %0, t; }"
        : "=r"(a) : "l"(p));
    return a;
}
__device__ __forceinline__ void cp16(uint32_t dst, const void* src) {
    asm volatile("cp.async.cg.shared.global [%0], [%1], 16;\n"
                 :: "r"(dst), "l"(src));
}
#define CP_COMMIT() asm volatile("cp.async.commit_group;" ::: "memory")
#define CP_WAIT0()  asm volatile("cp.async.wait_group 0;" ::: "memory")
#define CP_WAIT1()  asm volatile("cp.async.wait_group 1;" ::: "memory")
#define CP_WAIT2()  asm volatile("cp.async.wait_group 2;" ::: "memory")
#define SWZ128(x) ((x) ^ (((x) >> 3) & 0x70))

__device__ __forceinline__ void ldm4(uint32_t* a, uint32_t addr) {
    asm volatile("ldmatrix.sync.aligned.m8n8.x4.shared.b16 {%0,%1,%2,%3}, [%4];"
                 : "=r"(a[0]), "=r"(a[1]), "=r"(a[2]), "=r"(a[3]) : "r"(addr));
}
__device__ __forceinline__ void mma_f16(float* c, const uint32_t* a,
                                        uint32_t b0, uint32_t b1) {
    asm volatile(
        "mma.sync.aligned.m16n8k16.row.col.f32.f16.f16.f32 "
        "{%0,%1,%2,%3},{%4,%5,%6,%7},{%8,%9},{%0,%1,%2,%3};"
        : "+f"(c[0]), "+f"(c[1]), "+f"(c[2]), "+f"(c[3])
        : "r"(a[0]), "r"(a[1]), "r"(a[2]), "r"(a[3]), "r"(b0), "r"(b1));
}

// power-of-2 scale so max|g|*s <= 30000; identical math in every consumer
__device__ __forceinline__ float scale_of(int L) {
    float m = __uint_as_float(g_max_dev[L]);
    float s = 1.0f;
    if (m > 0.0f) s = exp2f(-ceilf(log2f(m / 30000.0f)));
    if (!(s > 0.0f) || isinf(s)) s = 1.0f;
    return s;
}

// ---------------------------------------------------------------------------
// Layer-1 fused kernel: converts A fp32 -> fp16 (writes a16_dev) AND computes
//   part[ks] = A @ G1.  BM=128, BK=64, 1 CTA/SM, 4 stages, distance 3.
// ---------------------------------------------------------------------------
__global__ void __launch_bounds__(256, 1)
conv_mma(const float* __restrict__ A) {
    constexpr int D    = 32;
    constexpr int NJ   = D / 16;           // 2
    constexpr int GPL  = D * 128;          // 4096
    constexpr int A32B = 128 * 256;        // 32768 (fp32 plane)
    constexpr int A16B = 128 * 128;        // 16384 (fp16 plane)
    constexpr int STAGE = A32B + A16B + GPL;  // 53248

    extern __shared__ __align__(1024) char smem[];
    const uint32_t sb = smem_u32(smem);
    const int tid  = threadIdx.x;
    const int wid  = tid >> 5;
    const int lane = tid & 31;
    const int rw   = wid >> 1;
    const int cw   = wid & 1;
    const size_t row0 = (size_t)blockIdx.x * 128;
    const size_t k0   = (size_t)blockIdx.y * KCH1;

    auto load_tile = [&](int st, int kt) {
        const uint32_t base = sb + st * STAGE;
        const size_t   ke   = k0 + (size_t)kt * BK;
        #pragma unroll
        for (int p = 0; p < 8; ++p) {
            const int c = p * 256 + tid;
            const int r = c >> 4, ch = c & 15;
            cp16(base + (uint32_t)(r * 256 + ch * 16),
                 A + (row0 + r) * NN + ke + ch * 4);
        }
        {
            const int r = tid >> 3, ch = tid & 7;
            cp16(base + A32B + A16B + SWZ128((uint32_t)(r * 128 + ch * 16)),
                 gt_h_dev + (size_t)r * NN + ke + ch * 8);
        }
    };

    float acc[2][NJ][4];
    #pragma unroll
    for (int mb = 0; mb < 2; ++mb)
        #pragma unroll
        for (int j = 0; j < NJ; ++j)
            #pragma unroll
            for (int q = 0; q < 4; ++q) acc[mb][j][q] = 0.0f;

    load_tile(0, 0); CP_COMMIT();
    load_tile(1, 1); CP_COMMIT();
    load_tile(2, 2); CP_COMMIT();

    for (int kt = 0; kt < NTILES1; ++kt) {
        if (kt < NTILES1 - 2)       CP_WAIT2();
        else if (kt == NTILES1 - 2) CP_WAIT1();
        else                        CP_WAIT0();
        __syncthreads();

        if (kt + 3 < NTILES1) { load_tile((kt + 3) & 3, kt + 3); CP_COMMIT(); }

        const int st = kt & 3;
        const uint32_t base = sb + st * STAGE;
        const size_t   ke   = k0 + (size_t)kt * BK;

        #pragma unroll
        for (int p = 0; p < 8; ++p) {
            const int c = p * 256 + tid;
            const int r = c >> 4, ch = c & 15;
            const float4 v = *(const float4*)(smem + st * STAGE + r * 256 + ch * 16);
            __half2 h01 = __floats2half2_rn(v.x, v.y);
            __half2 h23 = __floats2half2_rn(v.z, v.w);
            uint2 pk;
            pk.x = *reinterpret_cast<uint32_t*>(&h01);
            pk.y = *reinterpret_cast<uint32_t*>(&h23);
            *(uint2*)(a16_dev + (row0 + r) * NN + ke + ch * 4) = pk;
            *(uint2*)(smem + st * STAGE + A32B
                      + SWZ128((uint32_t)(r * 128 + ch * 8))) = pk;
        }
        __syncthreads();

        const uint32_t ab16 = base + A32B;
        uint32_t Ar[2][4][4];
        #pragma unroll
        for (int mb = 0; mb < 2; ++mb)
            #pragma unroll
            for (int kk = 0; kk < 4; ++kk)
                ldm4(Ar[mb][kk], ab16 + SWZ128((uint32_t)(
                    (rw * 32 + mb * 16 + (lane & 15)) * 128
                    + kk * 32 + (lane >> 4) * 16)));

        const uint32_t gb = base + A32B + A16B;
        #pragma unroll
        for (int j = 0; j < NJ; ++j) {
            const uint32_t nrow = (uint32_t)((cw * (D / 2) + j * 8 + (lane & 7)) * 128
                                             + (lane >> 3) * 16);
            uint32_t bh[8];
            ldm4(bh,     gb + SWZ128(nrow));
            ldm4(bh + 4, gb + SWZ128(nrow + 64));
            #pragma unroll
            for (int mb = 0; mb < 2; ++mb) {
                float* c = acc[mb][j];
                #pragma unroll
                for (int kk = 0; kk < 4; ++kk)
                    mma_f16(c, Ar[mb][kk], bh[2 * kk], bh[2 * kk + 1]);
            }
        }
    }

    float* P = part_buf_dev
             + ((size_t)blockIdx.y * NN + row0 + rw * 32) * D + cw * (D / 2);
    const int r0 = lane >> 2;
    const int c0 = (lane & 3) * 2;
    #pragma unroll
    for (int mb = 0; mb < 2; ++mb)
        #pragma unroll
        for (int j = 0; j < NJ; ++j) {
            float* c = acc[mb][j];
            *(float2*)&P[(size_t)(mb * 16 + r0) * D + j * 8 + c0]     = make_float2(c[0], c[1]);
            *(float2*)&P[(size_t)(mb * 16 + r0 + 8) * D + j * 8 + c0] = make_float2(c[2], c[3]);
        }
}

// ---------------------------------------------------------------------------
// Big GEMM (layers 2-4): part[ks] = A16 @ Gscaled_hi, 4 stages, distance 3.
// ---------------------------------------------------------------------------
template<int D>
__global__ void __launch_bounds__(256, 2)
big_mma() {
    constexpr int NJ    = D / 16;
    constexpr int GPL   = D * 128;
    constexpr int ATB   = 128 * 128;
    constexpr int STAGE = ATB + GPL;
    constexpr int GCHK  = D * 8;

    extern __shared__ __align__(1024) char smem[];
    const uint32_t sb = smem_u32(smem);
    const int tid  = threadIdx.x;
    const int wid  = tid >> 5;
    const int lane = tid & 31;
    const int rw   = wid >> 1;
    const int cw   = wid & 1;
    const size_t row0 = (size_t)blockIdx.x * 128;
    const size_t k0   = (size_t)blockIdx.y * KCH;

    auto load_tile = [&](int st, int kt) {
        const uint32_t base = sb + st * STAGE;
        const size_t   ke   = k0 + (size_t)kt * BK;
        #pragma unroll
        for (int p = 0; p < 4; ++p) {
            const int c = p * 256 + tid;
            const int r = c >> 3, ch = c & 7;
            cp16(base + SWZ128((uint32_t)(r * 128 + ch * 16)),
                 a16_dev + (row0 + r) * NN + ke + ch * 8);
        }
        #pragma unroll
        for (int p = 0; p < GCHK / 256; ++p) {
            const int c = p * 256 + tid;
            const int r = c >> 3, ch = c & 7;
            cp16(base + ATB + SWZ128((uint32_t)(r * 128 + ch * 16)),
                 gt_h_dev + (size_t)r * NN + ke + ch * 8);
        }
    };

    float acc[2][NJ][4];
    #pragma unroll
    for (int mb = 0; mb < 2; ++mb)
        #pragma unroll
        for (int j = 0; j < NJ; ++j)
            #pragma unroll
            for (int q = 0; q < 4; ++q) acc[mb][j][q] = 0.0f;

    load_tile(0, 0); CP_COMMIT();
    load_tile(1, 1); CP_COMMIT();
    load_tile(2, 2); CP_COMMIT();

    for (int kt = 0; kt < NTILES; ++kt) {
        if (kt < NTILES - 2)       CP_WAIT2();
        else if (kt == NTILES - 2) CP_WAIT1();
        else                       CP_WAIT0();
        __syncthreads();

        if (kt + 3 < NTILES) { load_tile((kt + 3) & 3, kt + 3); CP_COMMIT(); }

        const uint32_t base = sb + (kt & 3) * STAGE;

        uint32_t Ar[2][4][4];
        #pragma unroll
        for (int mb = 0; mb < 2; ++mb)
            #pragma unroll
            for (int kk = 0; kk < 4; ++kk)
                ldm4(Ar[mb][kk], base + SWZ128((uint32_t)(
                    (rw * 32 + mb * 16 + (lane & 15)) * 128
                    + kk * 32 + (lane >> 4) * 16)));

        const uint32_t gb = base + ATB;
        #pragma unroll
        for (int j = 0; j < NJ; ++j) {
            const uint32_t nrow = (uint32_t)((cw * (D / 2) + j * 8 + (lane & 7)) * 128
                                             + (lane >> 3) * 16);
            uint32_t bh[8];
            ldm4(bh,     gb + SWZ128(nrow));
            ldm4(bh + 4, gb + SWZ128(nrow + 64));
            #pragma unroll
            for (int mb = 0; mb < 2; ++mb) {
                float* c = acc[mb][j];
                #pragma unroll
                for (int kk = 0; kk < 4; ++kk)
                    mma_f16(c, Ar[mb][kk], bh[2 * kk], bh[2 * kk + 1]);
            }
        }
    }

    float* P = part_buf_dev
             + ((size_t)blockIdx.y * NN + row0 + rw * 32) * D + cw * (D / 2);
    const int r0 = lane >> 2;
    const int c0 = (lane & 3) * 2;
    #pragma unroll
    for (int mb = 0; mb < 2; ++mb)
        #pragma unroll
        for (int j = 0; j < NJ; ++j) {
            float* c = acc[mb][j];
            *(float2*)&P[(size_t)(mb * 16 + r0) * D + j * 8 + c0]     = make_float2(c[0], c[1]);
            *(float2*)&P[(size_t)(mb * 16 + r0 + 8) * D + j * 8 + c0] = make_float2(c[2], c[3]);
        }
}

// ---------------------------------------------------------------------------
// Row-wise: 4 threads per row; interleaved outputs j = q + 4*jj and padded
//   W stride (DIN+1) make the 4 distinct W rows per warp-step land in
//   adjacent banks -> conflict-free scalar LDS (was 4-way conflicted).
// ---------------------------------------------------------------------------
template<int DIN, int DOUT, int KS, bool RELU, int LAYER, int PREV>
__global__ void __launch_bounds__(256)
row_gemm(const float* __restrict__ xsrc, const float* __restrict__ W) {
    constexpr int JQ   = DOUT / 4;         // outputs per thread
    constexpr int WSTR = DIN + 1;          // padded row stride (floats)
    __shared__ float Ws[DOUT * WSTR];
    __shared__ float wmax[8];
    for (int i = threadIdx.x; i < DOUT * DIN; i += 256)
        Ws[(i / DIN) * WSTR + (i % DIN)] = W[i];
    __syncthreads();

    const float inv = (PREV >= 0) ? (1.0f / scale_of(PREV)) : 1.0f;
    const float* __restrict__ src = (PREV >= 0) ? part_buf_dev : xsrc;
    const int q = threadIdx.x & 3;         // output lane within row
    const int r = blockIdx.x * 64 + (threadIdx.x >> 2);

    float h[DIN];
    #pragma unroll
    for (int i4 = 0; i4 < DIN / 4; ++i4) {
        float4 v = *(const float4*)(src + (size_t)r * DIN + i4 * 4);
        h[4 * i4 + 0] = v.x; h[4 * i4 + 1] = v.y;
        h[4 * i4 + 2] = v.z; h[4 * i4 + 3] = v.w;
    }
    #pragma unroll
    for (int s = 1; s < KS; ++s)
        #pragma unroll
        for (int i4 = 0; i4 < DIN / 4; ++i4) {
            float4 v = *(const float4*)(src + ((size_t)s * NN + r) * DIN + i4 * 4);
            h[4 * i4 + 0] += v.x; h[4 * i4 + 1] += v.y;
            h[4 * i4 + 2] += v.z; h[4 * i4 + 3] += v.w;
        }
    #pragma unroll
    for (int i = 0; i < DIN; ++i) {
        h[i] *= inv;
        if (RELU) h[i] = fmaxf(h[i], 0.0f);
    }

    float m = 0.0f;
    #pragma unroll
    for (int jj = 0; jj < JQ; ++jj) {
        const int j = q + 4 * jj;          // interleaved: adjacent banks
        float a = 0.0f;
        const float* w = &Ws[j * WSTR];
        #pragma unroll
        for (int i = 0; i < DIN; ++i) a = fmaf(h[i], w[i], a);
        gt32_dev[(size_t)j * NN + r] = a;
        m = fmaxf(m, fabsf(a));
    }
    #pragma unroll
    for (int o = 16; o; o >>= 1)
        m = fmaxf(m, __shfl_xor_sync(0xFFFFFFFFu, m, o));
    if ((threadIdx.x & 31) == 0) wmax[threadIdx.x >> 5] = m;
    __syncthreads();
    if (threadIdx.x == 0) {
        float mm = wmax[0];
        #pragma unroll
        for (int w = 1; w < 8; ++w) mm = fmaxf(mm, wmax[w]);
        atomicMax(&g_max_dev[LAYER], __float_as_uint(mm));
    }
}

// ---------------------------------------------------------------------------
// Convert: G^T fp32 -> scaled fp16; fully coalesced
// ---------------------------------------------------------------------------
__global__ void __launch_bounds__(256)
convert_g(int L) {
    const size_t i = (size_t)blockIdx.x * 256 + threadIdx.x;
    const float s = scale_of(L);
    gt_h_dev[i] = __float2half_rn(gt32_dev[i] * s);
}

// ---------------------------------------------------------------------------
// Final reduce: out = inv_s4 * sum of KSPLIT partials
// ---------------------------------------------------------------------------
__global__ void __launch_bounds__(256)
reduce_out(float* __restrict__ out) {
    const int idx = blockIdx.x * 256 + threadIdx.x;
    const float4* p4 = (const float4*)part_buf_dev;
    float4 a = p4[idx];
    #pragma unroll
    for (int s = 1; s < KSPLIT; ++s) {
        float4 b = p4[(size_t)s * (NN * 32 / 4) + idx];
        a.x += b.x; a.y += b.y; a.z += b.z; a.w += b.w;
    }
    const float inv = 1.0f / scale_of(3);
    a.x *= inv; a.y *= inv; a.z *= inv; a.w *= inv;
    ((float4*)out)[idx] = a;
}

// ---------------------------------------------------------------------------
// Launch
// ---------------------------------------------------------------------------
extern "C" void kernel_launch(void* const* d_in, const int* in_sizes, int n_in,
                              void* d_out, int out_size) {
    (void)in_sizes; (void)n_in; (void)out_size;
    const float* A  = (const float*)d_in[0];
    const float* X  = (const float*)d_in[1];
    const float* W1 = (const float*)d_in[2];
    const float* W2 = (const float*)d_in[3];
    const float* W3 = (const float*)d_in[4];
    const float* W4 = (const float*)d_in[5];
    float* out = (float*)d_out;

    constexpr int SMC  = 4 * (32768 + 16384 + 32 * 128);   // 212992
    constexpr int SM32 = 4 * (16384 + 32 * 128);           // 81920
    constexpr int SM64 = 4 * (16384 + 64 * 128);           // 98304
    cudaFuncSetAttribute(conv_mma,    cudaFuncAttributeMaxDynamicSharedMemorySize, SMC);
    cudaFuncSetAttribute(big_mma<32>, cudaFuncAttributeMaxDynamicSharedMemorySize, SM32);
    cudaFuncSetAttribute(big_mma<64>, cudaFuncAttributeMaxDynamicSharedMemorySize, SM64);

    const dim3 big_grid(NN / 128, KSPLIT);     // 256 CTAs (single wave @2/SM)
    const dim3 conv_grid(NN / 128, KSPLIT1);   // 128 CTAs (single wave @1/SM)

    // Layer 1: G1 = X @ W1^T ; fused A-convert + P = A @ G1
    row_gemm<32, 32, 1, false, 0, -1><<<NN / 64, 256>>>(X, W1);
    convert_g<<<NN * 32 / 256, 256>>>(0);
    conv_mma<<<conv_grid, 256, SMC>>>(A);
    // Layer 2 (partials from layer 1 have KSPLIT1 splits)
    row_gemm<32, 64, KSPLIT1, true, 1, 0><<<NN / 64, 256>>>(nullptr, W2);
    convert_g<<<NN * 64 / 256, 256>>>(1);
    big_mma<64><<<big_grid, 256, SM64>>>();
    // Layer 3
    row_gemm<64, 64, KSPLIT, true, 2, 1><<<NN / 64, 256>>>(nullptr, W3);
    convert_g<<<NN * 64 / 256, 256>>>(2);
    big_mma<64><<<big_grid, 256, SM64>>>();
    // Layer 4
    row_gemm<64, 32, KSPLIT, true, 3, 2><<<NN / 64, 256>>>(nullptr, W4);
    convert_g<<<NN * 32 / 256, 256>>>(3);
    big_mma<32><<<big_grid, 256, SM32>>>();

    reduce_out<<<NN * 32 / 4 / 256, 256>>>(out);
}

// round 16
// speedup vs baseline: 1.3150x; 1.0478x over previous
#include <cuda_runtime.h>
#include <cuda_fp16.h>
#include <cstdint>

#define NN 8192
#define KSPLIT 4
#define KCH (NN / KSPLIT)          // 2048
#define BK 64
#define NTILES (KCH / BK)          // 32
#define KSPLIT1 2                  // layer-1 fused kernel (1 CTA/SM)
#define KCH1 (NN / KSPLIT1)        // 4096
#define NTILES1 (KCH1 / BK)        // 64

// ---------------------------------------------------------------------------
// Scratch (no cudaMalloc allowed)
// ---------------------------------------------------------------------------
__device__ __half a16_dev[(size_t)NN * NN];           // A in fp16 (128 MB)
__device__ __half gt_h_dev[64 * NN];                  // G^T hi [D][NN], scaled
__device__ float  gt32_dev[64 * NN];                  // G^T fp32 (true scale)
__device__ float  part_buf_dev[(size_t)KSPLIT * NN * 64];  // split-K partials
__device__ unsigned g_max_dev[4];                     // monotone across replays

// ---------------------------------------------------------------------------
// PTX helpers (plain sm_103-legal)
// ---------------------------------------------------------------------------
__device__ __forceinline__ uint32_t smem_u32(const void* p) {
    uint32_t a;
    asm("{ .reg .u64 t; cvta.to.shared.u64 t, %1; cvt.u32.u64 %0, t; }"
        : "=r"(a) : "l"(p));
    return a;
}
__device__ __forceinline__ void cp16(uint32_t dst, const void* src) {
    asm volatile("cp.async.cg.shared.global [%0], [%1], 16;\n"
                 :: "r"(dst), "l"(src));
}
#define CP_COMMIT() asm volatile("cp.async.commit_group;" ::: "memory")
#define CP_WAIT0()  asm volatile("cp.async.wait_group 0;" ::: "memory")
#define CP_WAIT1()  asm volatile("cp.async.wait_group 1;" ::: "memory")
#define CP_WAIT2()  asm volatile("cp.async.wait_group 2;" ::: "memory")
#define SWZ128(x) ((x) ^ (((x) >> 3) & 0x70))

__device__ __forceinline__ void ldm4(uint32_t* a, uint32_t addr) {
    asm volatile("ldmatrix.sync.aligned.m8n8.x4.shared.b16 {%0,%1,%2,%3}, [%4];"
                 : "=r"(a[0]), "=r"(a[1]), "=r"(a[2]), "=r"(a[3]) : "r"(addr));
}
__device__ __forceinline__ void mma_f16(float* c, const uint32_t* a,
                                        uint32_t b0, uint32_t b1) {
    asm volatile(
        "mma.sync.aligned.m16n8k16.row.col.f32.f16.f16.f32 "
        "{%0,%1,%2,%3},{%4,%5,%6,%7},{%8,%9},{%0,%1,%2,%3};"
        : "+f"(c[0]), "+f"(c[1]), "+f"(c[2]), "+f"(c[3])
        : "r"(a[0]), "r"(a[1]), "r"(a[2]), "r"(a[3]), "r"(b0), "r"(b1));
}

// power-of-2 scale so max|g|*s <= 30000; identical math in every consumer
__device__ __forceinline__ float scale_of(int L) {
    float m = __uint_as_float(g_max_dev[L]);
    float s = 1.0f;
    if (m > 0.0f) s = exp2f(-ceilf(log2f(m / 30000.0f)));
    if (!(s > 0.0f) || isinf(s)) s = 1.0f;
    return s;
}

// ---------------------------------------------------------------------------
// Layer-1 fused kernel: converts A fp32 -> fp16 (writes a16_dev) AND computes
//   part[ks] = A @ G1.  BM=128, BK=64, 1 CTA/SM, 4 stages, distance 3.
// ---------------------------------------------------------------------------
__global__ void __launch_bounds__(256, 1)
conv_mma(const float* __restrict__ A) {
    constexpr int D    = 32;
    constexpr int NJ   = D / 16;           // 2
    constexpr int GPL  = D * 128;          // 4096
    constexpr int A32B = 128 * 256;        // 32768 (fp32 plane)
    constexpr int A16B = 128 * 128;        // 16384 (fp16 plane)
    constexpr int STAGE = A32B + A16B + GPL;  // 53248

    extern __shared__ __align__(1024) char smem[];
    const uint32_t sb = smem_u32(smem);
    const int tid  = threadIdx.x;
    const int wid  = tid >> 5;
    const int lane = tid & 31;
    const int rw   = wid >> 1;
    const int cw   = wid & 1;
    const size_t row0 = (size_t)blockIdx.x * 128;
    const size_t k0   = (size_t)blockIdx.y * KCH1;

    auto load_tile = [&](int st, int kt) {
        const uint32_t base = sb + st * STAGE;
        const size_t   ke   = k0 + (size_t)kt * BK;
        #pragma unroll
        for (int p = 0; p < 8; ++p) {
            const int c = p * 256 + tid;
            const int r = c >> 4, ch = c & 15;
            cp16(base + (uint32_t)(r * 256 + ch * 16),
                 A + (row0 + r) * NN + ke + ch * 4);
        }
        {
            const int r = tid >> 3, ch = tid & 7;
            cp16(base + A32B + A16B + SWZ128((uint32_t)(r * 128 + ch * 16)),
                 gt_h_dev + (size_t)r * NN + ke + ch * 8);
        }
    };

    float acc[2][NJ][4];
    #pragma unroll
    for (int mb = 0; mb < 2; ++mb)
        #pragma unroll
        for (int j = 0; j < NJ; ++j)
            #pragma unroll
            for (int q = 0; q < 4; ++q) acc[mb][j][q] = 0.0f;

    load_tile(0, 0); CP_COMMIT();
    load_tile(1, 1); CP_COMMIT();
    load_tile(2, 2); CP_COMMIT();

    for (int kt = 0; kt < NTILES1; ++kt) {
        if (kt < NTILES1 - 2)       CP_WAIT2();
        else if (kt == NTILES1 - 2) CP_WAIT1();
        else                        CP_WAIT0();
        __syncthreads();

        if (kt + 3 < NTILES1) { load_tile((kt + 3) & 3, kt + 3); CP_COMMIT(); }

        const int st = kt & 3;
        const uint32_t base = sb + st * STAGE;
        const size_t   ke   = k0 + (size_t)kt * BK;

        #pragma unroll
        for (int p = 0; p < 8; ++p) {
            const int c = p * 256 + tid;
            const int r = c >> 4, ch = c & 15;
            const float4 v = *(const float4*)(smem + st * STAGE + r * 256 + ch * 16);
            __half2 h01 = __floats2half2_rn(v.x, v.y);
            __half2 h23 = __floats2half2_rn(v.z, v.w);
            uint2 pk;
            pk.x = *reinterpret_cast<uint32_t*>(&h01);
            pk.y = *reinterpret_cast<uint32_t*>(&h23);
            *(uint2*)(a16_dev + (row0 + r) * NN + ke + ch * 4) = pk;
            *(uint2*)(smem + st * STAGE + A32B
                      + SWZ128((uint32_t)(r * 128 + ch * 8))) = pk;
        }
        __syncthreads();

        const uint32_t ab16 = base + A32B;
        uint32_t Ar[2][4][4];
        #pragma unroll
        for (int mb = 0; mb < 2; ++mb)
            #pragma unroll
            for (int kk = 0; kk < 4; ++kk)
                ldm4(Ar[mb][kk], ab16 + SWZ128((uint32_t)(
                    (rw * 32 + mb * 16 + (lane & 15)) * 128
                    + kk * 32 + (lane >> 4) * 16)));

        const uint32_t gb = base + A32B + A16B;
        #pragma unroll
        for (int j = 0; j < NJ; ++j) {
            const uint32_t nrow = (uint32_t)((cw * (D / 2) + j * 8 + (lane & 7)) * 128
                                             + (lane >> 3) * 16);
            uint32_t bh[8];
            ldm4(bh,     gb + SWZ128(nrow));
            ldm4(bh + 4, gb + SWZ128(nrow + 64));
            #pragma unroll
            for (int mb = 0; mb < 2; ++mb) {
                float* c = acc[mb][j];
                #pragma unroll
                for (int kk = 0; kk < 4; ++kk)
                    mma_f16(c, Ar[mb][kk], bh[2 * kk], bh[2 * kk + 1]);
            }
        }
    }

    float* P = part_buf_dev
             + ((size_t)blockIdx.y * NN + row0 + rw * 32) * D + cw * (D / 2);
    const int r0 = lane >> 2;
    const int c0 = (lane & 3) * 2;
    #pragma unroll
    for (int mb = 0; mb < 2; ++mb)
        #pragma unroll
        for (int j = 0; j < NJ; ++j) {
            float* c = acc[mb][j];
            *(float2*)&P[(size_t)(mb * 16 + r0) * D + j * 8 + c0]     = make_float2(c[0], c[1]);
            *(float2*)&P[(size_t)(mb * 16 + r0 + 8) * D + j * 8 + c0] = make_float2(c[2], c[3]);
        }
}

// ---------------------------------------------------------------------------
// Big GEMM (layers 2-4): part[ks] = A16 @ Gscaled_hi, 4 stages, distance 3.
// ---------------------------------------------------------------------------
template<int D>
__global__ void __launch_bounds__(256, 2)
big_mma() {
    constexpr int NJ    = D / 16;
    constexpr int GPL   = D * 128;
    constexpr int ATB   = 128 * 128;
    constexpr int STAGE = ATB + GPL;
    constexpr int GCHK  = D * 8;

    extern __shared__ __align__(1024) char smem[];
    const uint32_t sb = smem_u32(smem);
    const int tid  = threadIdx.x;
    const int wid  = tid >> 5;
    const int lane = tid & 31;
    const int rw   = wid >> 1;
    const int cw   = wid & 1;
    const size_t row0 = (size_t)blockIdx.x * 128;
    const size_t k0   = (size_t)blockIdx.y * KCH;

    auto load_tile = [&](int st, int kt) {
        const uint32_t base = sb + st * STAGE;
        const size_t   ke   = k0 + (size_t)kt * BK;
        #pragma unroll
        for (int p = 0; p < 4; ++p) {
            const int c = p * 256 + tid;
            const int r = c >> 3, ch = c & 7;
            cp16(base + SWZ128((uint32_t)(r * 128 + ch * 16)),
                 a16_dev + (row0 + r) * NN + ke + ch * 8);
        }
        #pragma unroll
        for (int p = 0; p < GCHK / 256; ++p) {
            const int c = p * 256 + tid;
            const int r = c >> 3, ch = c & 7;
            cp16(base + ATB + SWZ128((uint32_t)(r * 128 + ch * 16)),
                 gt_h_dev + (size_t)r * NN + ke + ch * 8);
        }
    };

    float acc[2][NJ][4];
    #pragma unroll
    for (int mb = 0; mb < 2; ++mb)
        #pragma unroll
        for (int j = 0; j < NJ; ++j)
            #pragma unroll
            for (int q = 0; q < 4; ++q) acc[mb][j][q] = 0.0f;

    load_tile(0, 0); CP_COMMIT();
    load_tile(1, 1); CP_COMMIT();
    load_tile(2, 2); CP_COMMIT();

    for (int kt = 0; kt < NTILES; ++kt) {
        if (kt < NTILES - 2)       CP_WAIT2();
        else if (kt == NTILES - 2) CP_WAIT1();
        else                       CP_WAIT0();
        __syncthreads();

        if (kt + 3 < NTILES) { load_tile((kt + 3) & 3, kt + 3); CP_COMMIT(); }

        const uint32_t base = sb + (kt & 3) * STAGE;

        uint32_t Ar[2][4][4];
        #pragma unroll
        for (int mb = 0; mb < 2; ++mb)
            #pragma unroll
            for (int kk = 0; kk < 4; ++kk)
                ldm4(Ar[mb][kk], base + SWZ128((uint32_t)(
                    (rw * 32 + mb * 16 + (lane & 15)) * 128
                    + kk * 32 + (lane >> 4) * 16)));

        const uint32_t gb = base + ATB;
        #pragma unroll
        for (int j = 0; j < NJ; ++j) {
            const uint32_t nrow = (uint32_t)((cw * (D / 2) + j * 8 + (lane & 7)) * 128
                                             + (lane >> 3) * 16);
            uint32_t bh[8];
            ldm4(bh,     gb + SWZ128(nrow));
            ldm4(bh + 4, gb + SWZ128(nrow + 64));
            #pragma unroll
            for (int mb = 0; mb < 2; ++mb) {
                float* c = acc[mb][j];
                #pragma unroll
                for (int kk = 0; kk < 4; ++kk)
                    mma_f16(c, Ar[mb][kk], bh[2 * kk], bh[2 * kk + 1]);
            }
        }
    }

    float* P = part_buf_dev
             + ((size_t)blockIdx.y * NN + row0 + rw * 32) * D + cw * (D / 2);
    const int r0 = lane >> 2;
    const int c0 = (lane & 3) * 2;
    #pragma unroll
    for (int mb = 0; mb < 2; ++mb)
        #pragma unroll
        for (int j = 0; j < NJ; ++j) {
            float* c = acc[mb][j];
            *(float2*)&P[(size_t)(mb * 16 + r0) * D + j * 8 + c0]     = make_float2(c[0], c[1]);
            *(float2*)&P[(size_t)(mb * 16 + r0 + 8) * D + j * 8 + c0] = make_float2(c[2], c[3]);
        }
}

// ---------------------------------------------------------------------------
// Row-wise: 8 threads per row; interleaved outputs j = q + 8*jj and padded
//   W stride (DIN+1) keep the 8 distinct W rows per warp-step in adjacent
//   banks -> conflict-free scalar LDS. 32 rows/block, grid 256 (occ ~25%).
// ---------------------------------------------------------------------------
template<int DIN, int DOUT, int KS, bool RELU, int LAYER, int PREV>
__global__ void __launch_bounds__(256)
row_gemm(const float* __restrict__ xsrc, const float* __restrict__ W) {
    constexpr int JQ   = DOUT / 8;         // outputs per thread
    constexpr int WSTR = DIN + 1;          // padded row stride (floats)
    __shared__ float Ws[DOUT * WSTR];
    __shared__ float wmax[8];
    for (int i = threadIdx.x; i < DOUT * DIN; i += 256)
        Ws[(i / DIN) * WSTR + (i % DIN)] = W[i];
    __syncthreads();

    const float inv = (PREV >= 0) ? (1.0f / scale_of(PREV)) : 1.0f;
    const float* __restrict__ src = (PREV >= 0) ? part_buf_dev : xsrc;
    const int q = threadIdx.x & 7;         // output lane within row
    const int r = blockIdx.x * 32 + (threadIdx.x >> 3);

    float h[DIN];
    #pragma unroll
    for (int i4 = 0; i4 < DIN / 4; ++i4) {
        float4 v = *(const float4*)(src + (size_t)r * DIN + i4 * 4);
        h[4 * i4 + 0] = v.x; h[4 * i4 + 1] = v.y;
        h[4 * i4 + 2] = v.z; h[4 * i4 + 3] = v.w;
    }
    #pragma unroll
    for (int s = 1; s < KS; ++s)
        #pragma unroll
        for (int i4 = 0; i4 < DIN / 4; ++i4) {
            float4 v = *(const float4*)(src + ((size_t)s * NN + r) * DIN + i4 * 4);
            h[4 * i4 + 0] += v.x; h[4 * i4 + 1] += v.y;
            h[4 * i4 + 2] += v.z; h[4 * i4 + 3] += v.w;
        }
    #pragma unroll
    for (int i = 0; i < DIN; ++i) {
        h[i] *= inv;
        if (RELU) h[i] = fmaxf(h[i], 0.0f);
    }

    float m = 0.0f;
    #pragma unroll
    for (int jj = 0; jj < JQ; ++jj) {
        const int j = q + 8 * jj;          // interleaved: adjacent banks
        float a = 0.0f;
        const float* w = &Ws[j * WSTR];
        #pragma unroll
        for (int i = 0; i < DIN; ++i) a = fmaf(h[i], w[i], a);
        gt32_dev[(size_t)j * NN + r] = a;
        m = fmaxf(m, fabsf(a));
    }
    #pragma unroll
    for (int o = 16; o; o >>= 1)
        m = fmaxf(m, __shfl_xor_sync(0xFFFFFFFFu, m, o));
    if ((threadIdx.x & 31) == 0) wmax[threadIdx.x >> 5] = m;
    __syncthreads();
    if (threadIdx.x == 0) {
        float mm = wmax[0];
        #pragma unroll
        for (int w = 1; w < 8; ++w) mm = fmaxf(mm, wmax[w]);
        atomicMax(&g_max_dev[LAYER], __float_as_uint(mm));
    }
}

// ---------------------------------------------------------------------------
// Convert: G^T fp32 -> scaled fp16; fully coalesced
// ---------------------------------------------------------------------------
__global__ void __launch_bounds__(256)
convert_g(int L) {
    const size_t i = (size_t)blockIdx.x * 256 + threadIdx.x;
    const float s = scale_of(L);
    gt_h_dev[i] = __float2half_rn(gt32_dev[i] * s);
}

// ---------------------------------------------------------------------------
// Final reduce: out = inv_s4 * sum of KSPLIT partials
// ---------------------------------------------------------------------------
__global__ void __launch_bounds__(256)
reduce_out(float* __restrict__ out) {
    const int idx = blockIdx.x * 256 + threadIdx.x;
    const float4* p4 = (const float4*)part_buf_dev;
    float4 a = p4[idx];
    #pragma unroll
    for (int s = 1; s < KSPLIT; ++s) {
        float4 b = p4[(size_t)s * (NN * 32 / 4) + idx];
        a.x += b.x; a.y += b.y; a.z += b.z; a.w += b.w;
    }
    const float inv = 1.0f / scale_of(3);
    a.x *= inv; a.y *= inv; a.z *= inv; a.w *= inv;
    ((float4*)out)[idx] = a;
}

// ---------------------------------------------------------------------------
// Launch
// ---------------------------------------------------------------------------
extern "C" void kernel_launch(void* const* d_in, const int* in_sizes, int n_in,
                              void* d_out, int out_size) {
    (void)in_sizes; (void)n_in; (void)out_size;
    const float* A  = (const float*)d_in[0];
    const float* X  = (const float*)d_in[1];
    const float* W1 = (const float*)d_in[2];
    const float* W2 = (const float*)d_in[3];
    const float* W3 = (const float*)d_in[4];
    const float* W4 = (const float*)d_in[5];
    float* out = (float*)d_out;

    constexpr int SMC  = 4 * (32768 + 16384 + 32 * 128);   // 212992
    constexpr int SM32 = 4 * (16384 + 32 * 128);           // 81920
    constexpr int SM64 = 4 * (16384 + 64 * 128);           // 98304
    cudaFuncSetAttribute(conv_mma,    cudaFuncAttributeMaxDynamicSharedMemorySize, SMC);
    cudaFuncSetAttribute(big_mma<32>, cudaFuncAttributeMaxDynamicSharedMemorySize, SM32);
    cudaFuncSetAttribute(big_mma<64>, cudaFuncAttributeMaxDynamicSharedMemorySize, SM64);

    const dim3 big_grid(NN / 128, KSPLIT);     // 256 CTAs (single wave @2/SM)
    const dim3 conv_grid(NN / 128, KSPLIT1);   // 128 CTAs (single wave @1/SM)

    // Layer 1: G1 = X @ W1^T ; fused A-convert + P = A @ G1
    row_gemm<32, 32, 1, false, 0, -1><<<NN / 32, 256>>>(X, W1);
    convert_g<<<NN * 32 / 256, 256>>>(0);
    conv_mma<<<conv_grid, 256, SMC>>>(A);
    // Layer 2 (partials from layer 1 have KSPLIT1 splits)
    row_gemm<32, 64, KSPLIT1, true, 1, 0><<<NN / 32, 256>>>(nullptr, W2);
    convert_g<<<NN * 64 / 256, 256>>>(1);
    big_mma<64><<<big_grid, 256, SM64>>>();
    // Layer 3
    row_gemm<64, 64, KSPLIT, true, 2, 1><<<NN / 32, 256>>>(nullptr, W3);
    convert_g<<<NN * 64 / 256, 256>>>(2);
    big_mma<64><<<big_grid, 256, SM64>>>();
    // Layer 4
    row_gemm<64, 32, KSPLIT, true, 3, 2><<<NN / 32, 256>>>(nullptr, W4);
    convert_g<<<NN * 32 / 256, 256>>>(3);
    big_mma<32><<<big_grid, 256, SM32>>>();

    reduce_out<<<NN * 32 / 4 / 256, 256>>>(out);
}